// round 15
// baseline (speedup 1.0000x reference)
#include <cuda_runtime.h>

#define THREADS 256
#define NBN 2456                     // B*N = 8*307
#define OUT_ELEMS 10059776           // B*N*L*DM
#define TOTAL_ELEMS 50298880         // out + scores
#define QP 68                        // Qt pitch (transposed Q), lives inside Sc
// smem floats: A[4096] | Bm[4096] | C[4096] | Sc[16384] | Inv[256]  = 28928 = 115,712 B
#define SM_A 0
#define SM_B 4096
#define SM_C 8192
#define SM_SC 12288
#define SM_INV 28672
#define SMEM_FLOATS 28928            // proven 2-CTA/SM maximum
// inside Sc (floats, relative): Qt [0,4352) | Kbuf [4608,8704) | Wk [8704,12800)
#define SC_KBUF 4608
#define SC_WK 8704

__device__ __forceinline__ float elem4(const float4 v, int kk) {
    return (kk == 0) ? v.x : (kk == 1) ? v.y : (kk == 2) ? v.z : v.w;
}

// scores layout: head h, row q, 16B-granule g -> slot (g + q/4 + 4h) & 15
__device__ __forceinline__ int scIdx(int h, int q, int g) {
    return (h << 12) + (q << 6) + (((g + (q >> 2) + (h << 2)) & 15) << 2);
}

// linear 64x64 stage with 256 threads
__device__ __forceinline__ void stage64(float* __restrict__ dst, const float* __restrict__ src, int tid) {
#pragma unroll
    for (int i = 0; i < 4; i++)
        ((float4*)dst)[tid + i * THREADS] = __ldg((const float4*)src + tid + i * THREADS);
}

// linear 64x64 stage with 128 threads (t in [0,128))
__device__ __forceinline__ void stage64h(float* __restrict__ dst, const float* __restrict__ src, int t) {
#pragma unroll
    for (int i = 0; i < 8; i++)
        ((float4*)dst)[t + i * 128] = __ldg((const float4*)src + t + i * 128);
}

// acc[8][4] = X[64x64,p64] @ W[64x64,p64], 128-thread tiling (rows 8rx.., cols 4cx..).
// 12 LDS.128 per 128 FFMA.
__device__ __forceinline__ void gemm84(const float* __restrict__ X, const float* __restrict__ W,
                                       int rx, int cx, float acc[8][4]) {
    const int r0 = rx << 3, c0 = cx << 2;
#pragma unroll
    for (int i = 0; i < 8; i++)
#pragma unroll
        for (int j = 0; j < 4; j++) acc[i][j] = 0.f;
#pragma unroll 4
    for (int k4 = 0; k4 < 64; k4 += 4) {
        float4 xr[8], wv[4];
#pragma unroll
        for (int i = 0; i < 8; i++) xr[i] = *(const float4*)(X + ((r0 + i) << 6) + k4);
#pragma unroll
        for (int kk = 0; kk < 4; kk++) wv[kk] = *(const float4*)(W + ((k4 + kk) << 6) + c0);
#pragma unroll
        for (int kk = 0; kk < 4; kk++)
#pragma unroll
            for (int i = 0; i < 8; i++) {
                float a = elem4(xr[i], kk);
                acc[i][0] = fmaf(a, wv[kk].x, acc[i][0]);
                acc[i][1] = fmaf(a, wv[kk].y, acc[i][1]);
                acc[i][2] = fmaf(a, wv[kk].z, acc[i][2]);
                acc[i][3] = fmaf(a, wv[kk].w, acc[i][3]);
            }
    }
}

__global__ __launch_bounds__(THREADS, 2)
void mta_kernel(const float* __restrict__ gQ, const float* __restrict__ gK,
                const float* __restrict__ gV, const float* __restrict__ gMask,
                const float* __restrict__ gRes,
                const float* __restrict__ gWq, const float* __restrict__ gWk,
                const float* __restrict__ gWv, const float* __restrict__ gWfc,
                const float* __restrict__ gScale, const float* __restrict__ gBias,
                float* __restrict__ gOut, float* __restrict__ gScores,
                int write_scores) {
    extern __shared__ float sm[];
    float* A   = sm + SM_A;    // Xq -> Xv -> ctx       (pitch 64)
    float* Bm  = sm + SM_B;    // Wq -> Wv -> Wfc       (pitch 64)
    float* C   = sm + SM_C;    // Xk -> V' -> y         (pitch 64)
    float* Sc  = sm + SM_SC;   // Qt|Kbuf|Wk, then scores (rotation layout)
    float* Inv = sm + SM_INV;  // 1/colsum per (h,k)

    const int tid = threadIdx.x;
    const int bn = blockIdx.x;
    const float* xq = gQ + ((size_t)bn << 12);
    const float* xk = gK + ((size_t)bn << 12);
    const float* xv = gV + ((size_t)bn << 12);

    const int ty  = tid >> 4, tx  = tid & 15;   // AV tiling (256 thr)
    const int ty2 = tid & 15, tx2 = tid >> 4;   // QK tiling (256 thr)
    const int th  = tid & 127;                  // index within warp-group
    const int rx = th >> 4, cx = th & 15;       // 8x4 gemm tiling (128 thr)
    const bool wg0 = tid < 128;                 // warp-uniform

    // P0: stage Xq->A, Wq->Bm, Xk->C, Wk->Sc+SC_WK (16 LDG.128 in flight)
    stage64(A, xq, tid); stage64(Bm, gWq, tid);
    stage64(C, xk, tid); stage64(Sc + SC_WK, gWk, tid);
    __syncthreads();

    // P1: concurrent projections, SINGLE gemm84 body with warp-uniform operand select.
    //  wg0: Q = A @ Wq -> Qt (Sc, pitch QP, TRANSPOSED) ; wg1: K = C @ Wk -> Kbuf
    {
        const float* Xin = wg0 ? A : C;
        const float* Win = wg0 ? Bm : (Sc + SC_WK);
        float acc[8][4];
        gemm84(Xin, Win, rx, cx, acc);
        if (wg0) {
            float* Qt = Sc;
#pragma unroll
            for (int j = 0; j < 4; j++) {
                *(float4*)(Qt + ((cx << 2) + j) * QP + (rx << 3)) =
                    make_float4(acc[0][j], acc[1][j], acc[2][j], acc[3][j]);
                *(float4*)(Qt + ((cx << 2) + j) * QP + (rx << 3) + 4) =
                    make_float4(acc[4][j], acc[5][j], acc[6][j], acc[7][j]);
            }
        } else {
            float* Kb = Sc + SC_KBUF;
#pragma unroll
            for (int i = 0; i < 8; i++)
                *(float4*)(Kb + (((rx << 3) + i) << 6) + (cx << 2)) =
                    make_float4(acc[i][0], acc[i][1], acc[i][2], acc[i][3]);
        }
    }
    __syncthreads();

    // P2+P3: stage Xv->A, Wv->Bm (LDGs overlap) + QK from Qt/Kbuf, acc in regs
    stage64(A, xv, tid); stage64(Bm, gWv, tid);
    float sacc[4][4][4];
    {
        const float* Qt = Sc;
        const float* Kb = Sc + SC_KBUF;
#pragma unroll
        for (int h = 0; h < 4; h++)
#pragma unroll
            for (int i = 0; i < 4; i++)
#pragma unroll
                for (int j = 0; j < 4; j++) sacc[h][i][j] = 0.f;
#pragma unroll
        for (int h = 0; h < 4; h++)
#pragma unroll
            for (int d4 = 0; d4 < 4; d4++) {
                float4 Kv[4], Qv[4];
#pragma unroll
                for (int j = 0; j < 4; j++)
                    Kv[j] = *(const float4*)(Kb + (((tx2 << 2) + j) << 6) + (h << 4) + (d4 << 2));
#pragma unroll
                for (int dd = 0; dd < 4; dd++)
                    Qv[dd] = *(const float4*)(Qt + ((h << 4) + (d4 << 2) + dd) * QP + (ty2 << 2));
#pragma unroll
                for (int j = 0; j < 4; j++)
#pragma unroll
                    for (int dd = 0; dd < 4; dd++) {
                        float kd = elem4(Kv[j], dd);
                        sacc[h][0][j] = fmaf(Qv[dd].x, kd, sacc[h][0][j]);
                        sacc[h][1][j] = fmaf(Qv[dd].y, kd, sacc[h][1][j]);
                        sacc[h][2][j] = fmaf(Qv[dd].z, kd, sacc[h][2][j]);
                        sacc[h][3][j] = fmaf(Qv[dd].w, kd, sacc[h][3][j]);
                    }
            }
    }
    __syncthreads();   // Qt/Kbuf/Wk dead -> Sc becomes the scores tile

    // P4: masked raw scores * 0.25 -> Sc (rotation layout, sentinel -1e9f)
    {
        float m[4];
#pragma unroll
        for (int i = 0; i < 4; i++)
            m[i] = __ldg(gMask + (bn << 6) + (ty2 << 2) + i);
#pragma unroll
        for (int h = 0; h < 4; h++) {
            const int slot = ((tx2 + ty2 + (h << 2)) & 15) << 2;
#pragma unroll
            for (int i = 0; i < 4; i++) {
                const int q = (ty2 << 2) + i;
                bool msk = m[i] > 0.5f;
                *(float4*)(Sc + (h << 12) + (q << 6) + slot) = make_float4(
                    msk ? -1e9f : sacc[h][i][0] * 0.25f,
                    msk ? -1e9f : sacc[h][i][1] * 0.25f,
                    msk ? -1e9f : sacc[h][i][2] * 0.25f,
                    msk ? -1e9f : sacc[h][i][3] * 0.25f);
            }
        }
    }
    __syncthreads();

    // P5: wg0: V-gemm mainloop (8x4, acc in regs) || wg1: full softmax (2 cols/thread):
    //     +res_att, emit gmem scores, exp, colsum -> Inv.
    float vacc[8][4];
    if (wg0) {
        gemm84(A, Bm, rx, cx, vacc);
    } else {
#pragma unroll
        for (int cc = 0; cc < 2; cc++) {
            const int c = th + (cc << 7);        // columns th and th+128
            const int hh = c >> 6, kk2 = c & 63;
            const int g = kk2 >> 2, w = kk2 & 3;
            const float* resS = gRes + ((size_t)bn << 14) + (hh << 12) + kk2;
            float* soutS = write_scores ? gScores + ((size_t)bn << 14) + (hh << 12) + kk2 : nullptr;
            float ssum = 0.f;
#pragma unroll 4
            for (int q4 = 0; q4 < 16; q4++) {
                const int slot = ((g + q4 + (hh << 2)) & 15) << 2;
                float* p = Sc + (hh << 12) + (q4 << 8) + slot + w;
                float r0 = __ldg(resS + ((q4 << 2) + 0) * 64);
                float r1 = __ldg(resS + ((q4 << 2) + 1) * 64);
                float r2 = __ldg(resS + ((q4 << 2) + 2) * 64);
                float r3 = __ldg(resS + ((q4 << 2) + 3) * 64);
                float s0 = p[0], s1 = p[64], s2 = p[128], s3 = p[192];
                float o0 = (s0 == -1e9f) ? -1e9f : s0 + r0;
                float o1 = (s1 == -1e9f) ? -1e9f : s1 + r1;
                float o2 = (s2 == -1e9f) ? -1e9f : s2 + r2;
                float o3 = (s3 == -1e9f) ? -1e9f : s3 + r3;
                if (soutS) {
                    soutS[((q4 << 2) + 0) * 64] = o0;
                    soutS[((q4 << 2) + 1) * 64] = o1;
                    soutS[((q4 << 2) + 2) * 64] = o2;
                    soutS[((q4 << 2) + 3) * 64] = o3;
                }
                float e0 = __expf(o0), e1 = __expf(o1), e2 = __expf(o2), e3 = __expf(o3);
                p[0] = e0; p[64] = e1; p[128] = e2; p[192] = e3;
                ssum += (e0 + e1) + (e2 + e3);
            }
            Inv[c] = 1.0f / ssum;
        }
    }
    __syncthreads();

    // P6: wg0: V' = vacc * Inv[h, k-row] -> C  || wg1: stage Wfc -> Bm
    if (wg0) {
        const int hc = cx >> 2;
#pragma unroll
        for (int i = 0; i < 8; i++) {
            float iv = Inv[(hc << 6) + (rx << 3) + i];
            *(float4*)(C + (((rx << 3) + i) << 6) + (cx << 2)) =
                make_float4(vacc[i][0] * iv, vacc[i][1] * iv, vacc[i][2] * iv, vacc[i][3] * iv);
        }
    } else {
        stage64h(Bm, gWfc, th);
    }
    __syncthreads();

    // P7: ctx = exp @ V' -> A (256 threads; head hA = tx>>2)
    {
        const int hA = tx >> 2;
        float aacc[4][4];
#pragma unroll
        for (int i = 0; i < 4; i++)
#pragma unroll
            for (int j = 0; j < 4; j++) aacc[i][j] = 0.f;
#pragma unroll 4
        for (int g = 0; g < 16; g++) {
            float4 ar[4], vr[4];
#pragma unroll
            for (int i = 0; i < 4; i++)
                ar[i] = *(const float4*)(Sc + scIdx(hA, (ty << 2) + i, g));
#pragma unroll
            for (int kk = 0; kk < 4; kk++)
                vr[kk] = *(const float4*)(C + (((g << 2) + kk) << 6) + (tx << 2));
#pragma unroll
            for (int kk = 0; kk < 4; kk++)
#pragma unroll
                for (int i = 0; i < 4; i++) {
                    float a = elem4(ar[i], kk);
                    aacc[i][0] = fmaf(a, vr[kk].x, aacc[i][0]);
                    aacc[i][1] = fmaf(a, vr[kk].y, aacc[i][1]);
                    aacc[i][2] = fmaf(a, vr[kk].z, aacc[i][2]);
                    aacc[i][3] = fmaf(a, vr[kk].w, aacc[i][3]);
                }
        }
#pragma unroll
        for (int i = 0; i < 4; i++)
            *(float4*)(A + (((ty << 2) + i) << 6) + (tx << 2)) =
                make_float4(aacc[i][0], aacc[i][1], aacc[i][2], aacc[i][3]);
    }
    __syncthreads();

    // P8: wg0: y = ctx @ W_fc + input_Q -> C (8x4; full 64x64 coverage by 128 threads)
    if (wg0) {
        float acc[8][4];
        gemm84(A, Bm, rx, cx, acc);
#pragma unroll
        for (int i = 0; i < 8; i++) {
            float4 rr = __ldg((const float4*)(xq + (((rx << 3) + i) << 6) + (cx << 2)));
            *(float4*)(C + (((rx << 3) + i) << 6) + (cx << 2)) =
                make_float4(acc[i][0] + rr.x, acc[i][1] + rr.y,
                            acc[i][2] + rr.z, acc[i][3] + rr.w);
        }
    }
    __syncthreads();

    // P9: LayerNorm per row (warp-per-row, 256 threads) -> gOut
    {
        const int w = tid >> 5, ln = tid & 31;
        float s0 = __ldg(&gScale[ln]), s1 = __ldg(&gScale[ln + 32]);
        float b0 = __ldg(&gBias[ln]),  b1 = __ldg(&gBias[ln + 32]);
        float* outp = gOut + ((size_t)bn << 12);
#pragma unroll
        for (int rr = w; rr < 64; rr += 8) {
            float v0 = C[(rr << 6) + ln];
            float v1 = C[(rr << 6) + ln + 32];
            float s = v0 + v1;
#pragma unroll
            for (int o = 16; o > 0; o >>= 1) s += __shfl_xor_sync(0xffffffffu, s, o);
            float mu = s * 0.015625f;
            float d0 = v0 - mu, d1 = v1 - mu;
            float vv = d0 * d0 + d1 * d1;
#pragma unroll
            for (int o = 16; o > 0; o >>= 1) vv += __shfl_xor_sync(0xffffffffu, vv, o);
            float inv = rsqrtf(vv * 0.015625f + 1e-5f);
            outp[(rr << 6) + ln]      = fmaf(d0 * inv, s0, b0);
            outp[(rr << 6) + ln + 32] = fmaf(d1 * inv, s1, b1);
        }
    }
}

extern "C" void kernel_launch(void* const* d_in, const int* in_sizes, int n_in,
                              void* d_out, int out_size) {
    const float* gQ = (const float*)d_in[0];
    const float* gK = (const float*)d_in[1];
    const float* gV = (const float*)d_in[2];
    const float* gM = (const float*)d_in[3];
    const float* gR = (const float*)d_in[4];
    const float* wq = (const float*)d_in[5];
    const float* wk = (const float*)d_in[6];
    const float* wv = (const float*)d_in[7];
    const float* wf = (const float*)d_in[8];
    const float* ls = (const float*)d_in[9];
    const float* lb = (const float*)d_in[10];
    float* out = (float*)d_out;

    int write_scores = (out_size >= (int)TOTAL_ELEMS) ? 1 : 0;
    float* scores = out + OUT_ELEMS;

    size_t smem = (size_t)SMEM_FLOATS * sizeof(float);
    cudaFuncSetAttribute(mta_kernel, cudaFuncAttributeMaxDynamicSharedMemorySize, (int)smem);
    mta_kernel<<<NBN, THREADS, smem>>>(gQ, gK, gV, gM, gR, wq, wk, wv, wf, ls, lb,
                                       out, scores, write_scores);
}

// round 16
// speedup vs baseline: 1.0816x; 1.0816x over previous
#include <cuda_runtime.h>

#define THREADS 256
#define NBN 2456                     // B*N = 8*307
#define OUT_ELEMS 10059776           // B*N*L*DM
#define TOTAL_ELEMS 50298880         // out + scores
#define QP 68                        // Qt pitch (transposed Q), lives inside Sc
// smem floats: A[4096] | Bm[4096] | C[4096] | Sc[16384] | Inv[256]  = 28928 = 115,712 B
#define SM_A 0
#define SM_B 4096
#define SM_C 8192
#define SM_SC 12288
#define SM_INV 28672
#define SMEM_FLOATS 28928            // proven 2-CTA/SM maximum
// inside Sc (floats, relative): Qt [0,4352) | Kbuf [4608,8704) | Wk [8704,12800)
#define SC_KBUF 4608
#define SC_WK 8704

typedef unsigned long long u64;

__device__ __forceinline__ float elem4(const float4 v, int kk) {
    return (kk == 0) ? v.x : (kk == 1) ? v.y : (kk == 2) ? v.z : v.w;
}

// ---- packed f32x2 helpers (sm_103a) ----
__device__ __forceinline__ u64 pk2(float lo, float hi) {
    u64 r;
    asm("mov.b64 %0, {%1, %2};" : "=l"(r)
        : "r"(__float_as_uint(lo)), "r"(__float_as_uint(hi)));
    return r;
}
__device__ __forceinline__ u64 bc2(float x) { return pk2(x, x); }
__device__ __forceinline__ void fma2(u64& d, u64 a, u64 b) {
    asm("fma.rn.f32x2 %0, %1, %2, %0;" : "+l"(d) : "l"(a), "l"(b));
}
__device__ __forceinline__ void up2(u64 v, float& lo, float& hi) {
    unsigned int a, b;
    asm("mov.b64 {%0, %1}, %2;" : "=r"(a), "=r"(b) : "l"(v));
    lo = __uint_as_float(a); hi = __uint_as_float(b);
}

// scores layout: head h, row q, 16B-granule g -> slot (g + q/4 + 4h) & 15
__device__ __forceinline__ int scIdx(int h, int q, int g) {
    return (h << 12) + (q << 6) + (((g + (q >> 2) + (h << 2)) & 15) << 2);
}

// linear 64x64 stage with 256 threads
__device__ __forceinline__ void stage64(float* __restrict__ dst, const float* __restrict__ src, int tid) {
#pragma unroll
    for (int i = 0; i < 4; i++)
        ((float4*)dst)[tid + i * THREADS] = __ldg((const float4*)src + tid + i * THREADS);
}

// linear 64x64 stage with 128 threads (t in [0,128))
__device__ __forceinline__ void stage64h(float* __restrict__ dst, const float* __restrict__ src, int t) {
#pragma unroll
    for (int i = 0; i < 8; i++)
        ((float4*)dst)[t + i * 128] = __ldg((const float4*)src + t + i * 128);
}

// acc[8][4] = X[64x64,p64] @ W[64x64,p64], 128-thread tiling (rows 8rx.., cols 4cx..).
// Inner loop in fma.rn.f32x2: acc pairs over j, W pair free from float4 halves,
// scalar x broadcast-packed (alu pipe). Bit-identical to the scalar version.
__device__ __forceinline__ void gemm84(const float* __restrict__ X, const float* __restrict__ W,
                                       int rx, int cx, float acc[8][4]) {
    const int r0 = rx << 3, c0 = cx << 2;
    u64 acc2[8][2];
#pragma unroll
    for (int i = 0; i < 8; i++) { acc2[i][0] = 0ull; acc2[i][1] = 0ull; }
#pragma unroll 4
    for (int k4 = 0; k4 < 64; k4 += 4) {
        float4 xr[8], wv[4];
#pragma unroll
        for (int i = 0; i < 8; i++) xr[i] = *(const float4*)(X + ((r0 + i) << 6) + k4);
#pragma unroll
        for (int kk = 0; kk < 4; kk++) wv[kk] = *(const float4*)(W + ((k4 + kk) << 6) + c0);
#pragma unroll
        for (int kk = 0; kk < 4; kk++) {
            u64 w01 = pk2(wv[kk].x, wv[kk].y);
            u64 w23 = pk2(wv[kk].z, wv[kk].w);
#pragma unroll
            for (int i = 0; i < 8; i++) {
                u64 xb = bc2(elem4(xr[i], kk));
                fma2(acc2[i][0], xb, w01);
                fma2(acc2[i][1], xb, w23);
            }
        }
    }
#pragma unroll
    for (int i = 0; i < 8; i++) {
        up2(acc2[i][0], acc[i][0], acc[i][1]);
        up2(acc2[i][1], acc[i][2], acc[i][3]);
    }
}

__global__ __launch_bounds__(THREADS, 2)
void mta_kernel(const float* __restrict__ gQ, const float* __restrict__ gK,
                const float* __restrict__ gV, const float* __restrict__ gMask,
                const float* __restrict__ gRes,
                const float* __restrict__ gWq, const float* __restrict__ gWk,
                const float* __restrict__ gWv, const float* __restrict__ gWfc,
                const float* __restrict__ gScale, const float* __restrict__ gBias,
                float* __restrict__ gOut, float* __restrict__ gScores,
                int write_scores) {
    extern __shared__ float sm[];
    float* A   = sm + SM_A;    // Xq -> Xv -> ctx       (pitch 64)
    float* Bm  = sm + SM_B;    // Wq -> Wv -> Wfc       (pitch 64)
    float* C   = sm + SM_C;    // Xk -> V' -> y         (pitch 64)
    float* Sc  = sm + SM_SC;   // Qt|Kbuf|Wk, then scores (rotation layout)
    float* Inv = sm + SM_INV;  // 1/colsum per (h,k)

    const int tid = threadIdx.x;
    const int bn = blockIdx.x;
    const float* xq = gQ + ((size_t)bn << 12);
    const float* xk = gK + ((size_t)bn << 12);
    const float* xv = gV + ((size_t)bn << 12);

    const int ty  = tid >> 4, tx  = tid & 15;   // AV tiling (256 thr)
    const int ty2 = tid & 15, tx2 = tid >> 4;   // QK tiling (256 thr)
    const int th  = tid & 127;                  // index within warp-group
    const int rx = th >> 4, cx = th & 15;       // 8x4 gemm tiling (128 thr)
    const bool wg0 = tid < 128;                 // warp-uniform

    // P0: stage Xq->A, Wq->Bm, Xk->C, Wk->Sc+SC_WK (16 LDG.128 in flight)
    stage64(A, xq, tid); stage64(Bm, gWq, tid);
    stage64(C, xk, tid); stage64(Sc + SC_WK, gWk, tid);
    __syncthreads();

    // P1: concurrent projections, single gemm84 body with warp-uniform operand select.
    //  wg0: Q = A @ Wq -> Qt (Sc, pitch QP, TRANSPOSED) ; wg1: K = C @ Wk -> Kbuf
    {
        const float* Xin = wg0 ? A : C;
        const float* Win = wg0 ? Bm : (Sc + SC_WK);
        float acc[8][4];
        gemm84(Xin, Win, rx, cx, acc);
        if (wg0) {
            float* Qt = Sc;
#pragma unroll
            for (int j = 0; j < 4; j++) {
                *(float4*)(Qt + ((cx << 2) + j) * QP + (rx << 3)) =
                    make_float4(acc[0][j], acc[1][j], acc[2][j], acc[3][j]);
                *(float4*)(Qt + ((cx << 2) + j) * QP + (rx << 3) + 4) =
                    make_float4(acc[4][j], acc[5][j], acc[6][j], acc[7][j]);
            }
        } else {
            float* Kb = Sc + SC_KBUF;
#pragma unroll
            for (int i = 0; i < 8; i++)
                *(float4*)(Kb + (((rx << 3) + i) << 6) + (cx << 2)) =
                    make_float4(acc[i][0], acc[i][1], acc[i][2], acc[i][3]);
        }
    }
    __syncthreads();

    // P2+P3: stage Xv->A, Wv->Bm (LDGs overlap) + QK from Qt/Kbuf, acc in regs (scalar)
    stage64(A, xv, tid); stage64(Bm, gWv, tid);
    float sacc[4][4][4];
    {
        const float* Qt = Sc;
        const float* Kb = Sc + SC_KBUF;
#pragma unroll
        for (int h = 0; h < 4; h++)
#pragma unroll
            for (int i = 0; i < 4; i++)
#pragma unroll
                for (int j = 0; j < 4; j++) sacc[h][i][j] = 0.f;
#pragma unroll
        for (int h = 0; h < 4; h++)
#pragma unroll
            for (int d4 = 0; d4 < 4; d4++) {
                float4 Kv[4], Qv[4];
#pragma unroll
                for (int j = 0; j < 4; j++)
                    Kv[j] = *(const float4*)(Kb + (((tx2 << 2) + j) << 6) + (h << 4) + (d4 << 2));
#pragma unroll
                for (int dd = 0; dd < 4; dd++)
                    Qv[dd] = *(const float4*)(Qt + ((h << 4) + (d4 << 2) + dd) * QP + (ty2 << 2));
#pragma unroll
                for (int j = 0; j < 4; j++)
#pragma unroll
                    for (int dd = 0; dd < 4; dd++) {
                        float kd = elem4(Kv[j], dd);
                        sacc[h][0][j] = fmaf(Qv[dd].x, kd, sacc[h][0][j]);
                        sacc[h][1][j] = fmaf(Qv[dd].y, kd, sacc[h][1][j]);
                        sacc[h][2][j] = fmaf(Qv[dd].z, kd, sacc[h][2][j]);
                        sacc[h][3][j] = fmaf(Qv[dd].w, kd, sacc[h][3][j]);
                    }
            }
    }
    __syncthreads();   // Qt/Kbuf/Wk dead -> Sc becomes the scores tile

    // P4: masked raw scores * 0.25 -> Sc (rotation layout, sentinel -1e9f)
    {
        float m[4];
#pragma unroll
        for (int i = 0; i < 4; i++)
            m[i] = __ldg(gMask + (bn << 6) + (ty2 << 2) + i);
#pragma unroll
        for (int h = 0; h < 4; h++) {
            const int slot = ((tx2 + ty2 + (h << 2)) & 15) << 2;
#pragma unroll
            for (int i = 0; i < 4; i++) {
                const int q = (ty2 << 2) + i;
                bool msk = m[i] > 0.5f;
                *(float4*)(Sc + (h << 12) + (q << 6) + slot) = make_float4(
                    msk ? -1e9f : sacc[h][i][0] * 0.25f,
                    msk ? -1e9f : sacc[h][i][1] * 0.25f,
                    msk ? -1e9f : sacc[h][i][2] * 0.25f,
                    msk ? -1e9f : sacc[h][i][3] * 0.25f);
            }
        }
    }
    __syncthreads();

    // P5: wg0: V-gemm mainloop (8x4 f32x2, acc in regs) || wg1: full softmax (2 cols/thread)
    float vacc[8][4];
    if (wg0) {
        gemm84(A, Bm, rx, cx, vacc);
    } else {
#pragma unroll
        for (int cc = 0; cc < 2; cc++) {
            const int c = th + (cc << 7);        // columns th and th+128
            const int hh = c >> 6, kk2 = c & 63;
            const int g = kk2 >> 2, w = kk2 & 3;
            const float* resS = gRes + ((size_t)bn << 14) + (hh << 12) + kk2;
            float* soutS = write_scores ? gScores + ((size_t)bn << 14) + (hh << 12) + kk2 : nullptr;
            float ssum = 0.f;
#pragma unroll 4
            for (int q4 = 0; q4 < 16; q4++) {
                const int slot = ((g + q4 + (hh << 2)) & 15) << 2;
                float* p = Sc + (hh << 12) + (q4 << 8) + slot + w;
                float r0 = __ldg(resS + ((q4 << 2) + 0) * 64);
                float r1 = __ldg(resS + ((q4 << 2) + 1) * 64);
                float r2 = __ldg(resS + ((q4 << 2) + 2) * 64);
                float r3 = __ldg(resS + ((q4 << 2) + 3) * 64);
                float s0 = p[0], s1 = p[64], s2 = p[128], s3 = p[192];
                float o0 = (s0 == -1e9f) ? -1e9f : s0 + r0;
                float o1 = (s1 == -1e9f) ? -1e9f : s1 + r1;
                float o2 = (s2 == -1e9f) ? -1e9f : s2 + r2;
                float o3 = (s3 == -1e9f) ? -1e9f : s3 + r3;
                if (soutS) {
                    soutS[((q4 << 2) + 0) * 64] = o0;
                    soutS[((q4 << 2) + 1) * 64] = o1;
                    soutS[((q4 << 2) + 2) * 64] = o2;
                    soutS[((q4 << 2) + 3) * 64] = o3;
                }
                float e0 = __expf(o0), e1 = __expf(o1), e2 = __expf(o2), e3 = __expf(o3);
                p[0] = e0; p[64] = e1; p[128] = e2; p[192] = e3;
                ssum += (e0 + e1) + (e2 + e3);
            }
            Inv[c] = 1.0f / ssum;
        }
    }
    __syncthreads();

    // P6: wg0: V' = vacc * Inv[h, k-row] -> C  || wg1: stage Wfc -> Bm
    if (wg0) {
        const int hc = cx >> 2;
#pragma unroll
        for (int i = 0; i < 8; i++) {
            float iv = Inv[(hc << 6) + (rx << 3) + i];
            *(float4*)(C + (((rx << 3) + i) << 6) + (cx << 2)) =
                make_float4(vacc[i][0] * iv, vacc[i][1] * iv, vacc[i][2] * iv, vacc[i][3] * iv);
        }
    } else {
        stage64h(Bm, gWfc, th);
    }
    __syncthreads();

    // P7: ctx = exp @ V' -> A (256 threads; head hA = tx>>2), f32x2 inner loop
    {
        const int hA = tx >> 2;
        u64 aacc2[4][2];
#pragma unroll
        for (int i = 0; i < 4; i++) { aacc2[i][0] = 0ull; aacc2[i][1] = 0ull; }
#pragma unroll 4
        for (int g = 0; g < 16; g++) {
            float4 ar[4], vr[4];
#pragma unroll
            for (int i = 0; i < 4; i++)
                ar[i] = *(const float4*)(Sc + scIdx(hA, (ty << 2) + i, g));
#pragma unroll
            for (int kk = 0; kk < 4; kk++)
                vr[kk] = *(const float4*)(C + (((g << 2) + kk) << 6) + (tx << 2));
#pragma unroll
            for (int kk = 0; kk < 4; kk++) {
                u64 v01 = pk2(vr[kk].x, vr[kk].y);
                u64 v23 = pk2(vr[kk].z, vr[kk].w);
#pragma unroll
                for (int i = 0; i < 4; i++) {
                    u64 ab = bc2(elem4(ar[i], kk));
                    fma2(aacc2[i][0], ab, v01);
                    fma2(aacc2[i][1], ab, v23);
                }
            }
        }
#pragma unroll
        for (int i = 0; i < 4; i++) {
            float a0, a1, a2, a3;
            up2(aacc2[i][0], a0, a1);
            up2(aacc2[i][1], a2, a3);
            *(float4*)(A + (((ty << 2) + i) << 6) + (tx << 2)) =
                make_float4(a0, a1, a2, a3);
        }
    }
    __syncthreads();

    // P8: wg0: y = ctx @ W_fc + input_Q -> C (8x4 f32x2; full coverage by 128 threads)
    if (wg0) {
        float acc[8][4];
        gemm84(A, Bm, rx, cx, acc);
#pragma unroll
        for (int i = 0; i < 8; i++) {
            float4 rr = __ldg((const float4*)(xq + (((rx << 3) + i) << 6) + (cx << 2)));
            *(float4*)(C + (((rx << 3) + i) << 6) + (cx << 2)) =
                make_float4(acc[i][0] + rr.x, acc[i][1] + rr.y,
                            acc[i][2] + rr.z, acc[i][3] + rr.w);
        }
    }
    __syncthreads();

    // P9: LayerNorm per row (warp-per-row, 256 threads) -> gOut
    {
        const int w = tid >> 5, ln = tid & 31;
        float s0 = __ldg(&gScale[ln]), s1 = __ldg(&gScale[ln + 32]);
        float b0 = __ldg(&gBias[ln]),  b1 = __ldg(&gBias[ln + 32]);
        float* outp = gOut + ((size_t)bn << 12);
#pragma unroll
        for (int rr = w; rr < 64; rr += 8) {
            float v0 = C[(rr << 6) + ln];
            float v1 = C[(rr << 6) + ln + 32];
            float s = v0 + v1;
#pragma unroll
            for (int o = 16; o > 0; o >>= 1) s += __shfl_xor_sync(0xffffffffu, s, o);
            float mu = s * 0.015625f;
            float d0 = v0 - mu, d1 = v1 - mu;
            float vv = d0 * d0 + d1 * d1;
#pragma unroll
            for (int o = 16; o > 0; o >>= 1) vv += __shfl_xor_sync(0xffffffffu, vv, o);
            float inv = rsqrtf(vv * 0.015625f + 1e-5f);
            outp[(rr << 6) + ln]      = fmaf(d0 * inv, s0, b0);
            outp[(rr << 6) + ln + 32] = fmaf(d1 * inv, s1, b1);
        }
    }
}

extern "C" void kernel_launch(void* const* d_in, const int* in_sizes, int n_in,
                              void* d_out, int out_size) {
    const float* gQ = (const float*)d_in[0];
    const float* gK = (const float*)d_in[1];
    const float* gV = (const float*)d_in[2];
    const float* gM = (const float*)d_in[3];
    const float* gR = (const float*)d_in[4];
    const float* wq = (const float*)d_in[5];
    const float* wk = (const float*)d_in[6];
    const float* wv = (const float*)d_in[7];
    const float* wf = (const float*)d_in[8];
    const float* ls = (const float*)d_in[9];
    const float* lb = (const float*)d_in[10];
    float* out = (float*)d_out;

    int write_scores = (out_size >= (int)TOTAL_ELEMS) ? 1 : 0;
    float* scores = out + OUT_ELEMS;

    size_t smem = (size_t)SMEM_FLOATS * sizeof(float);
    cudaFuncSetAttribute(mta_kernel, cudaFuncAttributeMaxDynamicSharedMemorySize, (int)smem);
    mta_kernel<<<NBN, THREADS, smem>>>(gQ, gK, gV, gM, gR, wq, wk, wv, wf, ls, lb,
                                       out, scores, write_scores);
}